// round 7
// baseline (speedup 1.0000x reference)
#include <cuda_runtime.h>
#include <cuda_bf16.h>
#include <cuda_fp16.h>
#include <cstdint>

#define NN 50000
#define NE 800000

// ---------------- scratch (static __device__; no cudaMalloc) -----------------
__device__ float g_q[(size_t)NN * 128];
__device__ float g_k[(size_t)NN * 128];
__device__ float g_v[(size_t)NN * 128];
__device__ float g_alpha[NE];
__device__ uint2 g_msg[(size_t)NE * 32];   // fp16 messages, CSR order, 204.8MB
__device__ int   g_src[NE];
__device__ int   g_dst[NE];
__device__ int   g_eid[NE];
__device__ int   g_deg[NN];
__device__ int   g_cur[NN];
__device__ int   g_off[NN + 1];
__device__ int   g_is64;
// pre-split transposed weights: [out][n][k] bf16 (node: k=256, edge: k=64)
__device__ __nv_bfloat16 g_Wn_hi[4 * 128 * 256];
__device__ __nv_bfloat16 g_Wn_lo[4 * 128 * 256];
__device__ __nv_bfloat16 g_We_hi[128 * 64];
__device__ __nv_bfloat16 g_We_lo[128 * 64];

// ---------------- helpers ----------------------------------------------------
__device__ __forceinline__ uint32_t smem_u32(const void* p) {
    uint32_t a;
    asm("{ .reg .u64 t; cvta.to.shared.u64 t, %1; cvt.u32.u64 %0, t; }" : "=r"(a) : "l"(p));
    return a;
}
__device__ __forceinline__ uint32_t pkbf(float a, float b) {
    __nv_bfloat162 t = __floats2bfloat162_rn(a, b);
    return *reinterpret_cast<uint32_t*>(&t);
}
__device__ __forceinline__ void ldsm4(uint32_t* r, uint32_t addr) {
    asm volatile("ldmatrix.sync.aligned.m8n8.x4.shared.b16 {%0,%1,%2,%3}, [%4];"
                 : "=r"(r[0]), "=r"(r[1]), "=r"(r[2]), "=r"(r[3]) : "r"(addr));
}
__device__ __forceinline__ void mma16816(float* d, const uint32_t* a,
                                         uint32_t b0, uint32_t b1) {
    asm volatile(
        "mma.sync.aligned.m16n8k16.row.col.f32.bf16.bf16.f32 "
        "{%0,%1,%2,%3}, {%4,%5,%6,%7}, {%8,%9}, {%0,%1,%2,%3};"
        : "+f"(d[0]), "+f"(d[1]), "+f"(d[2]), "+f"(d[3])
        : "r"(a[0]), "r"(a[1]), "r"(a[2]), "r"(a[3]), "r"(b0), "r"(b1));
}
__device__ __forceinline__ void split4(float4 f, uint32_t& h0, uint32_t& h1,
                                       uint32_t& l0, uint32_t& l1) {
    float hx = __bfloat162float(__float2bfloat16_rn(f.x));
    float hy = __bfloat162float(__float2bfloat16_rn(f.y));
    float hz = __bfloat162float(__float2bfloat16_rn(f.z));
    float hw = __bfloat162float(__float2bfloat16_rn(f.w));
    h0 = pkbf(f.x, f.y);  h1 = pkbf(f.z, f.w);
    l0 = pkbf(f.x - hx, f.y - hy);
    l1 = pkbf(f.z - hz, f.w - hw);
}

// ---------------- dtype detection for edge_index -----------------------------
__global__ void detect_kernel(const unsigned int* __restrict__ p) {
    __shared__ unsigned red[256];
    unsigned v = 0;
    for (int i = threadIdx.x; i < 4096; i += 256) v |= p[2 * i + 1];
    red[threadIdx.x] = v;
    __syncthreads();
    for (int s = 128; s; s >>= 1) {
        if (threadIdx.x < s) red[threadIdx.x] |= red[threadIdx.x + s];
        __syncthreads();
    }
    if (threadIdx.x == 0) g_is64 = (red[0] == 0u) ? 1 : 0;
}

__global__ void zero_kernel() {
    int i = blockIdx.x * blockDim.x + threadIdx.x;
    if (i < NN) g_deg[i] = 0;
}

__global__ void prep_edges(const void* __restrict__ ei) {
    int i = blockIdx.x * blockDim.x + threadIdx.x;
    if (i >= NE) return;
    int src, dst;
    if (g_is64) {
        const long long* p = (const long long*)ei;
        src = (int)p[i];
        dst = (int)p[NE + i];
    } else {
        const int* p = (const int*)ei;
        src = p[i];
        dst = p[NE + i];
    }
    g_src[i] = src;
    g_dst[i] = dst;
    atomicAdd(&g_deg[dst], 1);
}

__global__ void scan_kernel() {
    __shared__ int sums[32];
    const int t = threadIdx.x, lane = t & 31, wid = t >> 5;
    int carry = 0;
    for (int base = 0; base < NN; base += 1024) {
        int i = base + t;
        int v = (i < NN) ? g_deg[i] : 0;
        int incl = v;
        #pragma unroll
        for (int o = 1; o < 32; o <<= 1) {
            int x = __shfl_up_sync(0xffffffffu, incl, o);
            if (lane >= o) incl += x;
        }
        if (lane == 31) sums[wid] = incl;
        __syncthreads();
        if (wid == 0) {
            int w = sums[lane];
            #pragma unroll
            for (int o = 1; o < 32; o <<= 1) {
                int x = __shfl_up_sync(0xffffffffu, w, o);
                if (lane >= o) w += x;
            }
            sums[lane] = w;
        }
        __syncthreads();
        int woff = wid ? sums[wid - 1] : 0;
        int excl = carry + woff + incl - v;
        if (i < NN) {
            g_off[i] = excl;
            g_cur[i] = excl;
        }
        carry += sums[31];
        __syncthreads();
    }
    if (t == 0) g_off[NN] = carry;
}

__global__ void scatter_kernel() {
    int i = blockIdx.x * blockDim.x + threadIdx.x;
    if (i >= NE) return;
    int dst = g_dst[i];
    int pos = atomicAdd(&g_cur[dst], 1);
    g_eid[pos] = i;
}

// ---------------- weight split/transpose -------------------------------------
__global__ void convert_w(const float* __restrict__ Wq, const float* __restrict__ Wk,
                          const float* __restrict__ Wv, const float* __restrict__ Ws,
                          const float* __restrict__ We) {
    int idx = blockIdx.x * 256 + threadIdx.x;
    if (idx < 4 * 128 * 256) {
        int o = idx >> 15, rem = idx & 32767, n = rem >> 8, k = rem & 255;
        const float* W = (o == 0) ? Wq : (o == 1) ? Wk : (o == 2) ? Wv : Ws;
        float v = W[k * 128 + n];
        __nv_bfloat16 h = __float2bfloat16_rn(v);
        g_Wn_hi[idx] = h;
        g_Wn_lo[idx] = __float2bfloat16_rn(v - __bfloat162float(h));
    }
    if (idx < 128 * 64) {
        int n = idx >> 6, k = idx & 63;
        float v = We[k * 128 + n];
        __nv_bfloat16 h = __float2bfloat16_rn(v);
        g_We_hi[idx] = h;
        g_We_lo[idx] = __float2bfloat16_rn(v - __bfloat162float(h));
    }
}

// ---------------- shared GEMM tile constants ---------------------------------
#define STG_BYTES 40960
#define S_AH(s) ((s) * STG_BYTES)
#define S_AL(s) ((s) * STG_BYTES + 10240)
#define S_BH(s) ((s) * STG_BYTES + 20480)
#define S_BL(s) ((s) * STG_BYTES + 30720)
#define GEMM_SMEM (2 * STG_BYTES)

// ---------------- node GEMM (q,k,v,skip), block 128x128, BK=32 ---------------
__global__ void __launch_bounds__(256) gemm_mma_node(
    const float* __restrict__ A, int M,
    const __nv_bfloat16* __restrict__ Whi, const __nv_bfloat16* __restrict__ Wlo,
    float* __restrict__ C0, float* __restrict__ C1,
    float* __restrict__ C2, float* __restrict__ C3,
    const float* __restrict__ b0, const float* __restrict__ b1,
    const float* __restrict__ b2, const float* __restrict__ b3) {
    constexpr int KDIM = 256;
    constexpr int NC = KDIM / 32;
    extern __shared__ char smem[];
    const uint32_t sbase = smem_u32(smem);
    const int tid = threadIdx.x;
    const int lane = tid & 31, wid = tid >> 5;
    const int warp_m = wid & 3, warp_n = wid >> 2;
    const int row0 = blockIdx.x * 128;
    const int oy = blockIdx.y;

    float* Csel = (oy == 0) ? C0 : (oy == 1) ? C1 : (oy == 2) ? C2 : C3;
    const float* bsel = (oy == 0) ? b0 : (oy == 1) ? b1 : (oy == 2) ? b2 : b3;
    const __nv_bfloat16* Wh = Whi + (size_t)oy * 128 * KDIM;
    const __nv_bfloat16* Wl = Wlo + (size_t)oy * 128 * KDIM;

    const int lrowA = tid >> 1;
    const int lhalf = tid & 1;
    int arow = row0 + lrowA;
    if (arow >= M) arow = M - 1;
    const float* aptr = A + (size_t)arow * KDIM + lhalf * 16;
    const __nv_bfloat16* whp = Wh + (size_t)lrowA * KDIM + lhalf * 16;
    const __nv_bfloat16* wlp = Wl + (size_t)lrowA * KDIM + lhalf * 16;
    const uint32_t sts_off = lrowA * 80 + lhalf * 32;

    float acc[2][8][4];
    #pragma unroll
    for (int mm = 0; mm < 2; mm++)
        #pragma unroll
        for (int nn = 0; nn < 8; nn++)
            #pragma unroll
            for (int i = 0; i < 4; i++) acc[mm][nn][i] = 0.f;

    float4 fA[4];
    uint4 wH0, wH1, wL0, wL1;

    #pragma unroll
    for (int j = 0; j < 4; j++) fA[j] = *(const float4*)(aptr + j * 4);
    wH0 = *(const uint4*)(whp);     wH1 = *(const uint4*)(whp + 8);
    wL0 = *(const uint4*)(wlp);     wL1 = *(const uint4*)(wlp + 8);
    {
        uint4 H0, H1, L0, L1;
        split4(fA[0], H0.x, H0.y, L0.x, L0.y);
        split4(fA[1], H0.z, H0.w, L0.z, L0.w);
        split4(fA[2], H1.x, H1.y, L1.x, L1.y);
        split4(fA[3], H1.z, H1.w, L1.z, L1.w);
        *(uint4*)(smem + S_AH(0) + sts_off) = H0;
        *(uint4*)(smem + S_AH(0) + sts_off + 16) = H1;
        *(uint4*)(smem + S_AL(0) + sts_off) = L0;
        *(uint4*)(smem + S_AL(0) + sts_off + 16) = L1;
        *(uint4*)(smem + S_BH(0) + sts_off) = wH0;
        *(uint4*)(smem + S_BH(0) + sts_off + 16) = wH1;
        *(uint4*)(smem + S_BL(0) + sts_off) = wL0;
        *(uint4*)(smem + S_BL(0) + sts_off + 16) = wL1;
    }
    __syncthreads();

    const int lrow = lane & 15;
    const int lcol = (lane >> 4) * 8;
    const uint32_t a_frag_off = (warp_m * 32 + lrow) * 80 + lcol * 2;
    const uint32_t b_frag_off = (warp_n * 64 + lrow) * 80 + lcol * 2;

    #pragma unroll
    for (int c = 0; c < NC; c++) {
        if (c + 1 < NC) {
            #pragma unroll
            for (int j = 0; j < 4; j++)
                fA[j] = *(const float4*)(aptr + (c + 1) * 32 + j * 4);
            wH0 = *(const uint4*)(whp + (c + 1) * 32);
            wH1 = *(const uint4*)(whp + (c + 1) * 32 + 8);
            wL0 = *(const uint4*)(wlp + (c + 1) * 32);
            wL1 = *(const uint4*)(wlp + (c + 1) * 32 + 8);
        }
        {
            const int st = c & 1;
            const uint32_t ah_b = sbase + S_AH(st) + a_frag_off;
            const uint32_t al_b = sbase + S_AL(st) + a_frag_off;
            const uint32_t bh_b = sbase + S_BH(st) + b_frag_off;
            const uint32_t bl_b = sbase + S_BL(st) + b_frag_off;
            #pragma unroll
            for (int k16 = 0; k16 < 2; k16++) {
                const uint32_t ko = k16 * 32;
                uint32_t ah[2][4], al[2][4];
                #pragma unroll
                for (int mm = 0; mm < 2; mm++) {
                    ldsm4(ah[mm], ah_b + mm * (16 * 80) + ko);
                    ldsm4(al[mm], al_b + mm * (16 * 80) + ko);
                }
                uint32_t bh[4][4], bl[4][4];
                #pragma unroll
                for (int p = 0; p < 4; p++) {
                    ldsm4(bh[p], bh_b + p * (16 * 80) + ko);
                    ldsm4(bl[p], bl_b + p * (16 * 80) + ko);
                }
                #pragma unroll
                for (int mm = 0; mm < 2; mm++) {
                    #pragma unroll
                    for (int p = 0; p < 4; p++) {
                        mma16816(acc[mm][2 * p + 0], ah[mm], bh[p][0], bh[p][2]);
                        mma16816(acc[mm][2 * p + 0], ah[mm], bl[p][0], bl[p][2]);
                        mma16816(acc[mm][2 * p + 0], al[mm], bh[p][0], bh[p][2]);
                        mma16816(acc[mm][2 * p + 1], ah[mm], bh[p][1], bh[p][3]);
                        mma16816(acc[mm][2 * p + 1], ah[mm], bl[p][1], bl[p][3]);
                        mma16816(acc[mm][2 * p + 1], al[mm], bh[p][1], bh[p][3]);
                    }
                }
            }
        }
        if (c + 1 < NC) {
            const int st = (c + 1) & 1;
            uint4 H0, H1, L0, L1;
            split4(fA[0], H0.x, H0.y, L0.x, L0.y);
            split4(fA[1], H0.z, H0.w, L0.z, L0.w);
            split4(fA[2], H1.x, H1.y, L1.x, L1.y);
            split4(fA[3], H1.z, H1.w, L1.z, L1.w);
            *(uint4*)(smem + S_AH(st) + sts_off) = H0;
            *(uint4*)(smem + S_AH(st) + sts_off + 16) = H1;
            *(uint4*)(smem + S_AL(st) + sts_off) = L0;
            *(uint4*)(smem + S_AL(st) + sts_off + 16) = L1;
            *(uint4*)(smem + S_BH(st) + sts_off) = wH0;
            *(uint4*)(smem + S_BH(st) + sts_off + 16) = wH1;
            *(uint4*)(smem + S_BL(st) + sts_off) = wL0;
            *(uint4*)(smem + S_BL(st) + sts_off + 16) = wL1;
        }
        __syncthreads();
    }

    const int grp = lane >> 2, tig = lane & 3;
    #pragma unroll
    for (int mm = 0; mm < 2; mm++) {
        const int r1 = row0 + warp_m * 32 + mm * 16 + grp;
        const int r2 = r1 + 8;
        #pragma unroll
        for (int nn = 0; nn < 8; nn++) {
            const int col = warp_n * 64 + nn * 8 + tig * 2;
            const float bx = bsel[col], by = bsel[col + 1];
            if (r1 < M) {
                float2 o = make_float2(acc[mm][nn][0] + bx, acc[mm][nn][1] + by);
                *(float2*)&Csel[(size_t)r1 * 128 + col] = o;
            }
            if (r2 < M) {
                float2 o = make_float2(acc[mm][nn][2] + bx, acc[mm][nn][3] + by);
                *(float2*)&Csel[(size_t)r2 * 128 + col] = o;
            }
        }
    }
}

// ---------------- fused edge GEMM + attention epilogue -----------------------
// Processes 128 edges per CTA IN CSR ORDER (gather edge_attr via g_eid).
// After e = edge_attr@We + be (in SMEM), per edge computes
//   alpha[j] = q[dst]·(k[src]+e) / sqrt(128)   (fp32)
//   msg[j]   = v[src] + e                      (fp16, CSR position -> streaming)
__global__ void __launch_bounds__(256) edge_gemm_fused(
    const float* __restrict__ EA, const float* __restrict__ be) {
    constexpr int NC = 2;   // K=64
    extern __shared__ char smem[];
    const uint32_t sbase = smem_u32(smem);
    const int tid = threadIdx.x;
    const int lane = tid & 31, wid = tid >> 5;
    const int warp_m = wid & 3, warp_n = wid >> 2;
    const int row0 = blockIdx.x * 128;

    const int lrowA = tid >> 1;
    const int lhalf = tid & 1;
    const int my_eid = g_eid[row0 + lrowA];
    const float* aptr = EA + (size_t)my_eid * 64 + lhalf * 16;
    const __nv_bfloat16* whp = g_We_hi + (size_t)lrowA * 64 + lhalf * 16;
    const __nv_bfloat16* wlp = g_We_lo + (size_t)lrowA * 64 + lhalf * 16;
    const uint32_t sts_off = lrowA * 80 + lhalf * 32;

    float acc[2][8][4];
    #pragma unroll
    for (int mm = 0; mm < 2; mm++)
        #pragma unroll
        for (int nn = 0; nn < 8; nn++)
            #pragma unroll
            for (int i = 0; i < 4; i++) acc[mm][nn][i] = 0.f;

    float4 fA[4];
    uint4 wH0, wH1, wL0, wL1;
    #pragma unroll
    for (int j = 0; j < 4; j++) fA[j] = *(const float4*)(aptr + j * 4);
    wH0 = *(const uint4*)(whp);     wH1 = *(const uint4*)(whp + 8);
    wL0 = *(const uint4*)(wlp);     wL1 = *(const uint4*)(wlp + 8);
    {
        uint4 H0, H1, L0, L1;
        split4(fA[0], H0.x, H0.y, L0.x, L0.y);
        split4(fA[1], H0.z, H0.w, L0.z, L0.w);
        split4(fA[2], H1.x, H1.y, L1.x, L1.y);
        split4(fA[3], H1.z, H1.w, L1.z, L1.w);
        *(uint4*)(smem + S_AH(0) + sts_off) = H0;
        *(uint4*)(smem + S_AH(0) + sts_off + 16) = H1;
        *(uint4*)(smem + S_AL(0) + sts_off) = L0;
        *(uint4*)(smem + S_AL(0) + sts_off + 16) = L1;
        *(uint4*)(smem + S_BH(0) + sts_off) = wH0;
        *(uint4*)(smem + S_BH(0) + sts_off + 16) = wH1;
        *(uint4*)(smem + S_BL(0) + sts_off) = wL0;
        *(uint4*)(smem + S_BL(0) + sts_off + 16) = wL1;
    }
    __syncthreads();

    const int lrow = lane & 15;
    const int lcol = (lane >> 4) * 8;
    const uint32_t a_frag_off = (warp_m * 32 + lrow) * 80 + lcol * 2;
    const uint32_t b_frag_off = (warp_n * 64 + lrow) * 80 + lcol * 2;

    #pragma unroll
    for (int c = 0; c < NC; c++) {
        if (c + 1 < NC) {
            #pragma unroll
            for (int j = 0; j < 4; j++)
                fA[j] = *(const float4*)(aptr + (c + 1) * 32 + j * 4);
            wH0 = *(const uint4*)(whp + (c + 1) * 32);
            wH1 = *(const uint4*)(whp + (c + 1) * 32 + 8);
            wL0 = *(const uint4*)(wlp + (c + 1) * 32);
            wL1 = *(const uint4*)(wlp + (c + 1) * 32 + 8);
        }
        {
            const int st = c & 1;
            const uint32_t ah_b = sbase + S_AH(st) + a_frag_off;
            const uint32_t al_b = sbase + S_AL(st) + a_frag_off;
            const uint32_t bh_b = sbase + S_BH(st) + b_frag_off;
            const uint32_t bl_b = sbase + S_BL(st) + b_frag_off;
            #pragma unroll
            for (int k16 = 0; k16 < 2; k16++) {
                const uint32_t ko = k16 * 32;
                uint32_t ah[2][4], al[2][4];
                #pragma unroll
                for (int mm = 0; mm < 2; mm++) {
                    ldsm4(ah[mm], ah_b + mm * (16 * 80) + ko);
                    ldsm4(al[mm], al_b + mm * (16 * 80) + ko);
                }
                uint32_t bh[4][4], bl[4][4];
                #pragma unroll
                for (int p = 0; p < 4; p++) {
                    ldsm4(bh[p], bh_b + p * (16 * 80) + ko);
                    ldsm4(bl[p], bl_b + p * (16 * 80) + ko);
                }
                #pragma unroll
                for (int mm = 0; mm < 2; mm++) {
                    #pragma unroll
                    for (int p = 0; p < 4; p++) {
                        mma16816(acc[mm][2 * p + 0], ah[mm], bh[p][0], bh[p][2]);
                        mma16816(acc[mm][2 * p + 0], ah[mm], bl[p][0], bl[p][2]);
                        mma16816(acc[mm][2 * p + 0], al[mm], bh[p][0], bh[p][2]);
                        mma16816(acc[mm][2 * p + 1], ah[mm], bh[p][1], bh[p][3]);
                        mma16816(acc[mm][2 * p + 1], ah[mm], bl[p][1], bl[p][3]);
                        mma16816(acc[mm][2 * p + 1], al[mm], bh[p][1], bh[p][3]);
                    }
                }
            }
        }
        if (c + 1 < NC) {
            const int st = (c + 1) & 1;
            uint4 H0, H1, L0, L1;
            split4(fA[0], H0.x, H0.y, L0.x, L0.y);
            split4(fA[1], H0.z, H0.w, L0.z, L0.w);
            split4(fA[2], H1.x, H1.y, L1.x, L1.y);
            split4(fA[3], H1.z, H1.w, L1.z, L1.w);
            *(uint4*)(smem + S_AH(st) + sts_off) = H0;
            *(uint4*)(smem + S_AH(st) + sts_off + 16) = H1;
            *(uint4*)(smem + S_AL(st) + sts_off) = L0;
            *(uint4*)(smem + S_AL(st) + sts_off + 16) = L1;
            *(uint4*)(smem + S_BH(st) + sts_off) = wH0;
            *(uint4*)(smem + S_BH(st) + sts_off + 16) = wH1;
            *(uint4*)(smem + S_BL(st) + sts_off) = wL0;
            *(uint4*)(smem + S_BL(st) + sts_off + 16) = wL1;
        }
        __syncthreads();
    }

    // ---- spill e tile (+bias) to SMEM fp32 [128][132] ----
    float* ew = (float*)smem;
    {
        const int grp = lane >> 2, tig = lane & 3;
        #pragma unroll
        for (int mm = 0; mm < 2; mm++) {
            const int r1 = warp_m * 32 + mm * 16 + grp;
            #pragma unroll
            for (int nn = 0; nn < 8; nn++) {
                const int col = warp_n * 64 + nn * 8 + tig * 2;
                const float bx = be[col], by = be[col + 1];
                ew[r1 * 132 + col]           = acc[mm][nn][0] + bx;
                ew[r1 * 132 + col + 1]       = acc[mm][nn][1] + by;
                ew[(r1 + 8) * 132 + col]     = acc[mm][nn][2] + bx;
                ew[(r1 + 8) * 132 + col + 1] = acc[mm][nn][3] + by;
            }
        }
    }
    __syncthreads();

    // ---- fused attention epilogue: each warp handles 16 edges ----
    #pragma unroll 1
    for (int t = 0; t < 16; t++) {
        const int lr = wid * 16 + t;       // local row
        const int j = row0 + lr;           // CSR position
        const int eid = g_eid[j];
        const int src = g_src[eid];
        const int dst = g_dst[eid];
        float4 e4 = *(const float4*)&ew[lr * 132 + lane * 4];
        float4 qq = *(const float4*)&g_q[(size_t)dst * 128 + lane * 4];
        float4 kk = *(const float4*)&g_k[(size_t)src * 128 + lane * 4];
        float4 vv = *(const float4*)&g_v[(size_t)src * 128 + lane * 4];
        float d = qq.x * (kk.x + e4.x) + qq.y * (kk.y + e4.y) +
                  qq.z * (kk.z + e4.z) + qq.w * (kk.w + e4.w);
        #pragma unroll
        for (int o = 16; o; o >>= 1) d += __shfl_xor_sync(0xffffffffu, d, o);
        if (lane == 0) g_alpha[j] = d * 0.08838834764831845f;
        __half2 m0 = __floats2half2_rn(vv.x + e4.x, vv.y + e4.y);
        __half2 m1 = __floats2half2_rn(vv.z + e4.z, vv.w + e4.w);
        uint2 pk;
        pk.x = *reinterpret_cast<uint32_t*>(&m0);
        pk.y = *reinterpret_cast<uint32_t*>(&m1);
        g_msg[(size_t)j * 32 + lane] = pk;
    }
}

// ---------------- streaming per-node softmax aggregation ---------------------
__global__ void __launch_bounds__(256) aggregate_kernel(float* __restrict__ out) {
    int warp = (blockIdx.x * blockDim.x + threadIdx.x) >> 5;
    int lane = threadIdx.x & 31;
    if (warp >= NN) return;
    const int n = warp;
    const int beg = g_off[n];
    const int end = g_off[n + 1];

    float m = -INFINITY, s = 0.f;
    float4 acc = make_float4(0.f, 0.f, 0.f, 0.f);

    if (beg < end) {
        // software pipeline: preload edge j before consuming edge j-1
        float alpha = g_alpha[beg];
        uint2 pk = g_msg[(size_t)beg * 32 + lane];
        for (int j = beg; j < end; j++) {
            float alpha_c = alpha;
            uint2 pk_c = pk;
            if (j + 1 < end) {
                alpha = g_alpha[j + 1];
                pk = g_msg[(size_t)(j + 1) * 32 + lane];
            }
            __half2 h0 = *reinterpret_cast<__half2*>(&pk_c.x);
            __half2 h1 = *reinterpret_cast<__half2*>(&pk_c.y);
            float2 f0 = __half22float2(h0);
            float2 f1 = __half22float2(h1);

            float mn = fmaxf(m, alpha_c);
            float corr = __expf(m - mn);
            float p = __expf(alpha_c - mn);
            s = s * corr + p;
            acc.x = acc.x * corr + p * f0.x;
            acc.y = acc.y * corr + p * f0.y;
            acc.z = acc.z * corr + p * f1.x;
            acc.w = acc.w * corr + p * f1.y;
            m = mn;
        }
    }

    float inv = 1.f / (s + 1e-16f);
    float4 sk = *(const float4*)&out[(size_t)n * 128 + lane * 4];
    float4 r;
    r.x = acc.x * inv + sk.x;
    r.y = acc.y * inv + sk.y;
    r.z = acc.z * inv + sk.z;
    r.w = acc.w * inv + sk.w;
    r.x = r.x > 0.f ? r.x : expm1f(r.x);
    r.y = r.y > 0.f ? r.y : expm1f(r.y);
    r.z = r.z > 0.f ? r.z : expm1f(r.z);
    r.w = r.w > 0.f ? r.w : expm1f(r.w);
    *(float4*)&out[(size_t)n * 128 + lane * 4] = r;
}

// ---------------- launch -----------------------------------------------------
extern "C" void kernel_launch(void* const* d_in, const int* in_sizes, int n_in,
                              void* d_out, int out_size) {
    const float* x  = (const float*)d_in[0];
    const void*  ei = d_in[1];
    const float* ea = (const float*)d_in[2];
    const float* Wq = (const float*)d_in[3];
    const float* bq = (const float*)d_in[4];
    const float* Wk = (const float*)d_in[5];
    const float* bk = (const float*)d_in[6];
    const float* Wv = (const float*)d_in[7];
    const float* bv = (const float*)d_in[8];
    const float* We = (const float*)d_in[9];
    const float* be = (const float*)d_in[10];
    const float* Ws = (const float*)d_in[11];
    const float* bs = (const float*)d_in[12];
    float* out = (float*)d_out;

    float *dq, *dk, *dv;
    __nv_bfloat16 *wnh, *wnl;
    cudaGetSymbolAddress((void**)&dq, g_q);
    cudaGetSymbolAddress((void**)&dk, g_k);
    cudaGetSymbolAddress((void**)&dv, g_v);
    cudaGetSymbolAddress((void**)&wnh, g_Wn_hi);
    cudaGetSymbolAddress((void**)&wnl, g_Wn_lo);

    cudaFuncSetAttribute(gemm_mma_node, cudaFuncAttributeMaxDynamicSharedMemorySize, GEMM_SMEM);
    cudaFuncSetAttribute(edge_gemm_fused, cudaFuncAttributeMaxDynamicSharedMemorySize, GEMM_SMEM);

    detect_kernel<<<1, 256>>>((const unsigned int*)ei);
    zero_kernel<<<(NN + 255) / 256, 256>>>();
    prep_edges<<<(NE + 255) / 256, 256>>>(ei);
    convert_w<<<512, 256>>>(Wq, Wk, Wv, Ws, We);
    scan_kernel<<<1, 1024>>>();
    scatter_kernel<<<(NE + 255) / 256, 256>>>();

    dim3 ngrid((NN + 127) / 128, 4);
    gemm_mma_node<<<ngrid, 256, GEMM_SMEM>>>(x, NN, wnh, wnl,
                                             dq, dk, dv, out,
                                             bq, bk, bv, bs);
    edge_gemm_fused<<<NE / 128, 256, GEMM_SMEM>>>(ea, be);

    aggregate_kernel<<<(NN * 32 + 255) / 256, 256>>>(out);
}

// round 12
// speedup vs baseline: 1.7423x; 1.7423x over previous
#include <cuda_runtime.h>
#include <cuda_bf16.h>
#include <cuda_fp16.h>
#include <cstdint>

#define NN 50000
#define NE 800000

// ---------------- scratch (static __device__; no cudaMalloc) -----------------
__device__ float  g_q[(size_t)NN * 128];
__device__ __half g_kh[(size_t)NN * 128];
__device__ __half g_vh[(size_t)NN * 128];
__device__ __half g_eh[(size_t)NE * 128];   // e in CSR order, fp16, 204.8MB
__device__ int   g_src[NE];
__device__ int   g_dst[NE];
__device__ int   g_eid[NE];
__device__ int   g_csrc[NE];                // src per CSR position
__device__ int   g_deg[NN];
__device__ int   g_cur[NN];
__device__ int   g_off[NN + 1];
__device__ int   g_is64;
// pre-split transposed weights: [out][n][k] bf16 (node: k=256, edge: k=64)
__device__ __nv_bfloat16 g_Wn_hi[4 * 128 * 256];
__device__ __nv_bfloat16 g_Wn_lo[4 * 128 * 256];
__device__ __nv_bfloat16 g_We_hi[128 * 64];
__device__ __nv_bfloat16 g_We_lo[128 * 64];

// ---------------- helpers ----------------------------------------------------
__device__ __forceinline__ uint32_t smem_u32(const void* p) {
    uint32_t a;
    asm("{ .reg .u64 t; cvta.to.shared.u64 t, %1; cvt.u32.u64 %0, t; }" : "=r"(a) : "l"(p));
    return a;
}
__device__ __forceinline__ uint32_t pkbf(float a, float b) {
    __nv_bfloat162 t = __floats2bfloat162_rn(a, b);
    return *reinterpret_cast<uint32_t*>(&t);
}
__device__ __forceinline__ void ldsm4(uint32_t* r, uint32_t addr) {
    asm volatile("ldmatrix.sync.aligned.m8n8.x4.shared.b16 {%0,%1,%2,%3}, [%4];"
                 : "=r"(r[0]), "=r"(r[1]), "=r"(r[2]), "=r"(r[3]) : "r"(addr));
}
__device__ __forceinline__ void mma16816(float* d, const uint32_t* a,
                                         uint32_t b0, uint32_t b1) {
    asm volatile(
        "mma.sync.aligned.m16n8k16.row.col.f32.bf16.bf16.f32 "
        "{%0,%1,%2,%3}, {%4,%5,%6,%7}, {%8,%9}, {%0,%1,%2,%3};"
        : "+f"(d[0]), "+f"(d[1]), "+f"(d[2]), "+f"(d[3])
        : "r"(a[0]), "r"(a[1]), "r"(a[2]), "r"(a[3]), "r"(b0), "r"(b1));
}
__device__ __forceinline__ void split4(float4 f, uint32_t& h0, uint32_t& h1,
                                       uint32_t& l0, uint32_t& l1) {
    float hx = __bfloat162float(__float2bfloat16_rn(f.x));
    float hy = __bfloat162float(__float2bfloat16_rn(f.y));
    float hz = __bfloat162float(__float2bfloat16_rn(f.z));
    float hw = __bfloat162float(__float2bfloat16_rn(f.w));
    h0 = pkbf(f.x, f.y);  h1 = pkbf(f.z, f.w);
    l0 = pkbf(f.x - hx, f.y - hy);
    l1 = pkbf(f.z - hz, f.w - hw);
}
__device__ __forceinline__ uint32_t pkh2(float a, float b) {
    __half2 t = __floats2half2_rn(a, b);
    return *reinterpret_cast<uint32_t*>(&t);
}
__device__ __forceinline__ float4 upk_h4(uint2 pk) {
    __half2 h0 = *reinterpret_cast<__half2*>(&pk.x);
    __half2 h1 = *reinterpret_cast<__half2*>(&pk.y);
    float2 a = __half22float2(h0), b = __half22float2(h1);
    return make_float4(a.x, a.y, b.x, b.y);
}

// ---------------- dtype detection for edge_index -----------------------------
__global__ void detect_kernel(const unsigned int* __restrict__ p) {
    __shared__ unsigned red[256];
    unsigned v = 0;
    for (int i = threadIdx.x; i < 4096; i += 256) v |= p[2 * i + 1];
    red[threadIdx.x] = v;
    __syncthreads();
    for (int s = 128; s; s >>= 1) {
        if (threadIdx.x < s) red[threadIdx.x] |= red[threadIdx.x + s];
        __syncthreads();
    }
    if (threadIdx.x == 0) g_is64 = (red[0] == 0u) ? 1 : 0;
}

__global__ void zero_kernel() {
    int i = blockIdx.x * blockDim.x + threadIdx.x;
    if (i < NN) g_deg[i] = 0;
}

__global__ void prep_edges(const void* __restrict__ ei) {
    int i = blockIdx.x * blockDim.x + threadIdx.x;
    if (i >= NE) return;
    int src, dst;
    if (g_is64) {
        const long long* p = (const long long*)ei;
        src = (int)p[i];
        dst = (int)p[NE + i];
    } else {
        const int* p = (const int*)ei;
        src = p[i];
        dst = p[NE + i];
    }
    g_src[i] = src;
    g_dst[i] = dst;
    atomicAdd(&g_deg[dst], 1);
}

__global__ void scan_kernel() {
    __shared__ int sums[32];
    const int t = threadIdx.x, lane = t & 31, wid = t >> 5;
    int carry = 0;
    for (int base = 0; base < NN; base += 1024) {
        int i = base + t;
        int v = (i < NN) ? g_deg[i] : 0;
        int incl = v;
        #pragma unroll
        for (int o = 1; o < 32; o <<= 1) {
            int x = __shfl_up_sync(0xffffffffu, incl, o);
            if (lane >= o) incl += x;
        }
        if (lane == 31) sums[wid] = incl;
        __syncthreads();
        if (wid == 0) {
            int w = sums[lane];
            #pragma unroll
            for (int o = 1; o < 32; o <<= 1) {
                int x = __shfl_up_sync(0xffffffffu, w, o);
                if (lane >= o) w += x;
            }
            sums[lane] = w;
        }
        __syncthreads();
        int woff = wid ? sums[wid - 1] : 0;
        int excl = carry + woff + incl - v;
        if (i < NN) {
            g_off[i] = excl;
            g_cur[i] = excl;
        }
        carry += sums[31];
        __syncthreads();
    }
    if (t == 0) g_off[NN] = carry;
}

__global__ void scatter_kernel() {
    int i = blockIdx.x * blockDim.x + threadIdx.x;
    if (i >= NE) return;
    int dst = g_dst[i];
    int src = g_src[i];
    int pos = atomicAdd(&g_cur[dst], 1);
    g_eid[pos] = i;
    g_csrc[pos] = src;
}

// ---------------- weight split/transpose -------------------------------------
__global__ void convert_w(const float* __restrict__ Wq, const float* __restrict__ Wk,
                          const float* __restrict__ Wv, const float* __restrict__ Ws,
                          const float* __restrict__ We) {
    int idx = blockIdx.x * 256 + threadIdx.x;
    if (idx < 4 * 128 * 256) {
        int o = idx >> 15, rem = idx & 32767, n = rem >> 8, k = rem & 255;
        const float* W = (o == 0) ? Wq : (o == 1) ? Wk : (o == 2) ? Wv : Ws;
        float v = W[k * 128 + n];
        __nv_bfloat16 h = __float2bfloat16_rn(v);
        g_Wn_hi[idx] = h;
        g_Wn_lo[idx] = __float2bfloat16_rn(v - __bfloat162float(h));
    }
    if (idx < 128 * 64) {
        int n = idx >> 6, k = idx & 63;
        float v = We[k * 128 + n];
        __nv_bfloat16 h = __float2bfloat16_rn(v);
        g_We_hi[idx] = h;
        g_We_lo[idx] = __float2bfloat16_rn(v - __bfloat162float(h));
    }
}

// ---------------- shared GEMM tile constants ---------------------------------
#define STG_BYTES 40960
#define S_AH(s) ((s) * STG_BYTES)
#define S_AL(s) ((s) * STG_BYTES + 10240)
#define S_BH(s) ((s) * STG_BYTES + 20480)
#define S_BL(s) ((s) * STG_BYTES + 30720)
#define GEMM_SMEM (2 * STG_BYTES)

// ---------------- node GEMM (q,k,v,skip), block 128x128, BK=32 ---------------
// oy=0 -> q (fp32), oy=1 -> k (fp16), oy=2 -> v (fp16), oy=3 -> skip (fp32 out)
__global__ void __launch_bounds__(256) gemm_mma_node(
    const float* __restrict__ A, int M,
    const __nv_bfloat16* __restrict__ Whi, const __nv_bfloat16* __restrict__ Wlo,
    float* __restrict__ Cq, __half* __restrict__ Ck,
    __half* __restrict__ Cv, float* __restrict__ Cs,
    const float* __restrict__ b0, const float* __restrict__ b1,
    const float* __restrict__ b2, const float* __restrict__ b3) {
    constexpr int KDIM = 256;
    constexpr int NC = KDIM / 32;
    extern __shared__ char smem[];
    const uint32_t sbase = smem_u32(smem);
    const int tid = threadIdx.x;
    const int lane = tid & 31, wid = tid >> 5;
    const int warp_m = wid & 3, warp_n = wid >> 2;
    const int row0 = blockIdx.x * 128;
    const int oy = blockIdx.y;

    const float* bsel = (oy == 0) ? b0 : (oy == 1) ? b1 : (oy == 2) ? b2 : b3;
    const __nv_bfloat16* Wh = Whi + (size_t)oy * 128 * KDIM;
    const __nv_bfloat16* Wl = Wlo + (size_t)oy * 128 * KDIM;

    const int lrowA = tid >> 1;
    const int lhalf = tid & 1;
    int arow = row0 + lrowA;
    if (arow >= M) arow = M - 1;
    const float* aptr = A + (size_t)arow * KDIM + lhalf * 16;
    const __nv_bfloat16* whp = Wh + (size_t)lrowA * KDIM + lhalf * 16;
    const __nv_bfloat16* wlp = Wl + (size_t)lrowA * KDIM + lhalf * 16;
    const uint32_t sts_off = lrowA * 80 + lhalf * 32;

    float acc[2][8][4];
    #pragma unroll
    for (int mm = 0; mm < 2; mm++)
        #pragma unroll
        for (int nn = 0; nn < 8; nn++)
            #pragma unroll
            for (int i = 0; i < 4; i++) acc[mm][nn][i] = 0.f;

    float4 fA[4];
    uint4 wH0, wH1, wL0, wL1;

    #pragma unroll
    for (int j = 0; j < 4; j++) fA[j] = *(const float4*)(aptr + j * 4);
    wH0 = *(const uint4*)(whp);     wH1 = *(const uint4*)(whp + 8);
    wL0 = *(const uint4*)(wlp);     wL1 = *(const uint4*)(wlp + 8);
    {
        uint4 H0, H1, L0, L1;
        split4(fA[0], H0.x, H0.y, L0.x, L0.y);
        split4(fA[1], H0.z, H0.w, L0.z, L0.w);
        split4(fA[2], H1.x, H1.y, L1.x, L1.y);
        split4(fA[3], H1.z, H1.w, L1.z, L1.w);
        *(uint4*)(smem + S_AH(0) + sts_off) = H0;
        *(uint4*)(smem + S_AH(0) + sts_off + 16) = H1;
        *(uint4*)(smem + S_AL(0) + sts_off) = L0;
        *(uint4*)(smem + S_AL(0) + sts_off + 16) = L1;
        *(uint4*)(smem + S_BH(0) + sts_off) = wH0;
        *(uint4*)(smem + S_BH(0) + sts_off + 16) = wH1;
        *(uint4*)(smem + S_BL(0) + sts_off) = wL0;
        *(uint4*)(smem + S_BL(0) + sts_off + 16) = wL1;
    }
    __syncthreads();

    const int lrow = lane & 15;
    const int lcol = (lane >> 4) * 8;
    const uint32_t a_frag_off = (warp_m * 32 + lrow) * 80 + lcol * 2;
    const uint32_t b_frag_off = (warp_n * 64 + lrow) * 80 + lcol * 2;

    #pragma unroll
    for (int c = 0; c < NC; c++) {
        if (c + 1 < NC) {
            #pragma unroll
            for (int j = 0; j < 4; j++)
                fA[j] = *(const float4*)(aptr + (c + 1) * 32 + j * 4);
            wH0 = *(const uint4*)(whp + (c + 1) * 32);
            wH1 = *(const uint4*)(whp + (c + 1) * 32 + 8);
            wL0 = *(const uint4*)(wlp + (c + 1) * 32);
            wL1 = *(const uint4*)(wlp + (c + 1) * 32 + 8);
        }
        {
            const int st = c & 1;
            const uint32_t ah_b = sbase + S_AH(st) + a_frag_off;
            const uint32_t al_b = sbase + S_AL(st) + a_frag_off;
            const uint32_t bh_b = sbase + S_BH(st) + b_frag_off;
            const uint32_t bl_b = sbase + S_BL(st) + b_frag_off;
            #pragma unroll
            for (int k16 = 0; k16 < 2; k16++) {
                const uint32_t ko = k16 * 32;
                uint32_t ah[2][4], al[2][4];
                #pragma unroll
                for (int mm = 0; mm < 2; mm++) {
                    ldsm4(ah[mm], ah_b + mm * (16 * 80) + ko);
                    ldsm4(al[mm], al_b + mm * (16 * 80) + ko);
                }
                uint32_t bh[4][4], bl[4][4];
                #pragma unroll
                for (int p = 0; p < 4; p++) {
                    ldsm4(bh[p], bh_b + p * (16 * 80) + ko);
                    ldsm4(bl[p], bl_b + p * (16 * 80) + ko);
                }
                #pragma unroll
                for (int mm = 0; mm < 2; mm++) {
                    #pragma unroll
                    for (int p = 0; p < 4; p++) {
                        mma16816(acc[mm][2 * p + 0], ah[mm], bh[p][0], bh[p][2]);
                        mma16816(acc[mm][2 * p + 0], ah[mm], bl[p][0], bl[p][2]);
                        mma16816(acc[mm][2 * p + 0], al[mm], bh[p][0], bh[p][2]);
                        mma16816(acc[mm][2 * p + 1], ah[mm], bh[p][1], bh[p][3]);
                        mma16816(acc[mm][2 * p + 1], ah[mm], bl[p][1], bl[p][3]);
                        mma16816(acc[mm][2 * p + 1], al[mm], bh[p][1], bh[p][3]);
                    }
                }
            }
        }
        if (c + 1 < NC) {
            const int st = (c + 1) & 1;
            uint4 H0, H1, L0, L1;
            split4(fA[0], H0.x, H0.y, L0.x, L0.y);
            split4(fA[1], H0.z, H0.w, L0.z, L0.w);
            split4(fA[2], H1.x, H1.y, L1.x, L1.y);
            split4(fA[3], H1.z, H1.w, L1.z, L1.w);
            *(uint4*)(smem + S_AH(st) + sts_off) = H0;
            *(uint4*)(smem + S_AH(st) + sts_off + 16) = H1;
            *(uint4*)(smem + S_AL(st) + sts_off) = L0;
            *(uint4*)(smem + S_AL(st) + sts_off + 16) = L1;
            *(uint4*)(smem + S_BH(st) + sts_off) = wH0;
            *(uint4*)(smem + S_BH(st) + sts_off + 16) = wH1;
            *(uint4*)(smem + S_BL(st) + sts_off) = wL0;
            *(uint4*)(smem + S_BL(st) + sts_off + 16) = wL1;
        }
        __syncthreads();
    }

    const int grp = lane >> 2, tig = lane & 3;
    const bool is_half = (oy == 1) || (oy == 2);
    __half* Hsel = (oy == 1) ? Ck : Cv;
    float* Fsel = (oy == 0) ? Cq : Cs;
    #pragma unroll
    for (int mm = 0; mm < 2; mm++) {
        const int r1 = row0 + warp_m * 32 + mm * 16 + grp;
        const int r2 = r1 + 8;
        #pragma unroll
        for (int nn = 0; nn < 8; nn++) {
            const int col = warp_n * 64 + nn * 8 + tig * 2;
            const float bx = bsel[col], by = bsel[col + 1];
            if (is_half) {
                if (r1 < M) {
                    uint32_t h = pkh2(acc[mm][nn][0] + bx, acc[mm][nn][1] + by);
                    *(uint32_t*)&Hsel[(size_t)r1 * 128 + col] = h;
                }
                if (r2 < M) {
                    uint32_t h = pkh2(acc[mm][nn][2] + bx, acc[mm][nn][3] + by);
                    *(uint32_t*)&Hsel[(size_t)r2 * 128 + col] = h;
                }
            } else {
                if (r1 < M) {
                    float2 o = make_float2(acc[mm][nn][0] + bx, acc[mm][nn][1] + by);
                    *(float2*)&Fsel[(size_t)r1 * 128 + col] = o;
                }
                if (r2 < M) {
                    float2 o = make_float2(acc[mm][nn][2] + bx, acc[mm][nn][3] + by);
                    *(float2*)&Fsel[(size_t)r2 * 128 + col] = o;
                }
            }
        }
    }
}

// ---------------- edge GEMM, CSR-ordered, fp16 output ------------------------
// Row j of output = e for the edge at CSR position row0+j (gather EA via g_eid).
// Output written SEQUENTIALLY in CSR order as fp16.
__global__ void __launch_bounds__(256) edge_gemm_csr(
    const float* __restrict__ EA, const float* __restrict__ be) {
    constexpr int NC = 2;   // K=64
    extern __shared__ char smem[];
    const uint32_t sbase = smem_u32(smem);
    const int tid = threadIdx.x;
    const int lane = tid & 31, wid = tid >> 5;
    const int warp_m = wid & 3, warp_n = wid >> 2;
    const int row0 = blockIdx.x * 128;

    const int lrowA = tid >> 1;
    const int lhalf = tid & 1;
    const int my_eid = g_eid[row0 + lrowA];
    const float* aptr = EA + (size_t)my_eid * 64 + lhalf * 16;
    const __nv_bfloat16* whp = g_We_hi + (size_t)lrowA * 64 + lhalf * 16;
    const __nv_bfloat16* wlp = g_We_lo + (size_t)lrowA * 64 + lhalf * 16;
    const uint32_t sts_off = lrowA * 80 + lhalf * 32;

    float acc[2][8][4];
    #pragma unroll
    for (int mm = 0; mm < 2; mm++)
        #pragma unroll
        for (int nn = 0; nn < 8; nn++)
            #pragma unroll
            for (int i = 0; i < 4; i++) acc[mm][nn][i] = 0.f;

    float4 fA[4];
    uint4 wH0, wH1, wL0, wL1;
    #pragma unroll
    for (int j = 0; j < 4; j++) fA[j] = *(const float4*)(aptr + j * 4);
    wH0 = *(const uint4*)(whp);     wH1 = *(const uint4*)(whp + 8);
    wL0 = *(const uint4*)(wlp);     wL1 = *(const uint4*)(wlp + 8);
    {
        uint4 H0, H1, L0, L1;
        split4(fA[0], H0.x, H0.y, L0.x, L0.y);
        split4(fA[1], H0.z, H0.w, L0.z, L0.w);
        split4(fA[2], H1.x, H1.y, L1.x, L1.y);
        split4(fA[3], H1.z, H1.w, L1.z, L1.w);
        *(uint4*)(smem + S_AH(0) + sts_off) = H0;
        *(uint4*)(smem + S_AH(0) + sts_off + 16) = H1;
        *(uint4*)(smem + S_AL(0) + sts_off) = L0;
        *(uint4*)(smem + S_AL(0) + sts_off + 16) = L1;
        *(uint4*)(smem + S_BH(0) + sts_off) = wH0;
        *(uint4*)(smem + S_BH(0) + sts_off + 16) = wH1;
        *(uint4*)(smem + S_BL(0) + sts_off) = wL0;
        *(uint4*)(smem + S_BL(0) + sts_off + 16) = wL1;
    }
    __syncthreads();

    const int lrow = lane & 15;
    const int lcol = (lane >> 4) * 8;
    const uint32_t a_frag_off = (warp_m * 32 + lrow) * 80 + lcol * 2;
    const uint32_t b_frag_off = (warp_n * 64 + lrow) * 80 + lcol * 2;

    #pragma unroll
    for (int c = 0; c < NC; c++) {
        if (c + 1 < NC) {
            #pragma unroll
            for (int j = 0; j < 4; j++)
                fA[j] = *(const float4*)(aptr + (c + 1) * 32 + j * 4);
            wH0 = *(const uint4*)(whp + (c + 1) * 32);
            wH1 = *(const uint4*)(whp + (c + 1) * 32 + 8);
            wL0 = *(const uint4*)(wlp + (c + 1) * 32);
            wL1 = *(const uint4*)(wlp + (c + 1) * 32 + 8);
        }
        {
            const int st = c & 1;
            const uint32_t ah_b = sbase + S_AH(st) + a_frag_off;
            const uint32_t al_b = sbase + S_AL(st) + a_frag_off;
            const uint32_t bh_b = sbase + S_BH(st) + b_frag_off;
            const uint32_t bl_b = sbase + S_BL(st) + b_frag_off;
            #pragma unroll
            for (int k16 = 0; k16 < 2; k16++) {
                const uint32_t ko = k16 * 32;
                uint32_t ah[2][4], al[2][4];
                #pragma unroll
                for (int mm = 0; mm < 2; mm++) {
                    ldsm4(ah[mm], ah_b + mm * (16 * 80) + ko);
                    ldsm4(al[mm], al_b + mm * (16 * 80) + ko);
                }
                uint32_t bh[4][4], bl[4][4];
                #pragma unroll
                for (int p = 0; p < 4; p++) {
                    ldsm4(bh[p], bh_b + p * (16 * 80) + ko);
                    ldsm4(bl[p], bl_b + p * (16 * 80) + ko);
                }
                #pragma unroll
                for (int mm = 0; mm < 2; mm++) {
                    #pragma unroll
                    for (int p = 0; p < 4; p++) {
                        mma16816(acc[mm][2 * p + 0], ah[mm], bh[p][0], bh[p][2]);
                        mma16816(acc[mm][2 * p + 0], ah[mm], bl[p][0], bl[p][2]);
                        mma16816(acc[mm][2 * p + 0], al[mm], bh[p][0], bh[p][2]);
                        mma16816(acc[mm][2 * p + 1], ah[mm], bh[p][1], bh[p][3]);
                        mma16816(acc[mm][2 * p + 1], ah[mm], bl[p][1], bl[p][3]);
                        mma16816(acc[mm][2 * p + 1], al[mm], bh[p][1], bh[p][3]);
                    }
                }
            }
        }
        if (c + 1 < NC) {
            const int st = (c + 1) & 1;
            uint4 H0, H1, L0, L1;
            split4(fA[0], H0.x, H0.y, L0.x, L0.y);
            split4(fA[1], H0.z, H0.w, L0.z, L0.w);
            split4(fA[2], H1.x, H1.y, L1.x, L1.y);
            split4(fA[3], H1.z, H1.w, L1.z, L1.w);
            *(uint4*)(smem + S_AH(st) + sts_off) = H0;
            *(uint4*)(smem + S_AH(st) + sts_off + 16) = H1;
            *(uint4*)(smem + S_AL(st) + sts_off) = L0;
            *(uint4*)(smem + S_AL(st) + sts_off + 16) = L1;
            *(uint4*)(smem + S_BH(st) + sts_off) = wH0;
            *(uint4*)(smem + S_BH(st) + sts_off + 16) = wH1;
            *(uint4*)(smem + S_BL(st) + sts_off) = wL0;
            *(uint4*)(smem + S_BL(st) + sts_off + 16) = wL1;
        }
        __syncthreads();
    }

    // ---- spill e tile (+bias) to SMEM fp32 [128][132] ----
    float* ew = (float*)smem;
    {
        const int grp = lane >> 2, tig = lane & 3;
        #pragma unroll
        for (int mm = 0; mm < 2; mm++) {
            const int r1 = warp_m * 32 + mm * 16 + grp;
            #pragma unroll
            for (int nn = 0; nn < 8; nn++) {
                const int col = warp_n * 64 + nn * 8 + tig * 2;
                const float bx = be[col], by = be[col + 1];
                ew[r1 * 132 + col]           = acc[mm][nn][0] + bx;
                ew[r1 * 132 + col + 1]       = acc[mm][nn][1] + by;
                ew[(r1 + 8) * 132 + col]     = acc[mm][nn][2] + bx;
                ew[(r1 + 8) * 132 + col + 1] = acc[mm][nn][3] + by;
            }
        }
    }
    __syncthreads();

    // ---- vectorized fp16 streaming store, CSR order ----
    #pragma unroll
    for (int it = 0; it < 16; it++) {
        const int idx = it * 256 + tid;       // 0..4095
        const int row = idx >> 5;
        const int c4 = (idx & 31) * 4;        // column group of 4
        float4 f;
        f.x = ew[row * 132 + c4];
        f.y = ew[row * 132 + c4 + 1];
        f.z = ew[row * 132 + c4 + 2];
        f.w = ew[row * 132 + c4 + 3];
        uint2 o;
        o.x = pkh2(f.x, f.y);
        o.y = pkh2(f.z, f.w);
        *(uint2*)&g_eh[(size_t)(row0 + row) * 128 + c4] = o;
    }
}

// ---------------- per-node online-softmax aggregation (1 warp / node) --------
// e read sequentially (fp16, CSR), k/v gathered (fp16, L2-resident).
__global__ void __launch_bounds__(256) aggregate_kernel(float* __restrict__ out) {
    int warp = (blockIdx.x * blockDim.x + threadIdx.x) >> 5;
    int lane = threadIdx.x & 31;
    if (warp >= NN) return;
    const int n = warp;
    const int beg = g_off[n];
    const int end = g_off[n + 1];

    float4 q = *(const float4*)&g_q[(size_t)n * 128 + lane * 4];
    float m = -INFINITY, s = 0.f;
    float4 acc = make_float4(0.f, 0.f, 0.f, 0.f);

    if (beg < end) {
        // software pipeline one edge ahead
        int src = g_csrc[beg];
        uint2 epk = *(const uint2*)&g_eh[(size_t)beg * 128 + lane * 4];
        uint2 kpk = *(const uint2*)&g_kh[(size_t)src * 128 + lane * 4];
        uint2 vpk = *(const uint2*)&g_vh[(size_t)src * 128 + lane * 4];
        for (int j = beg; j < end; j++) {
            uint2 ec = epk, kc = kpk, vc = vpk;
            if (j + 1 < end) {
                int nsrc = g_csrc[j + 1];
                epk = *(const uint2*)&g_eh[(size_t)(j + 1) * 128 + lane * 4];
                kpk = *(const uint2*)&g_kh[(size_t)nsrc * 128 + lane * 4];
                vpk = *(const uint2*)&g_vh[(size_t)nsrc * 128 + lane * 4];
            }
            float4 e4 = upk_h4(ec);
            float4 k4 = upk_h4(kc);
            float4 v4 = upk_h4(vc);

            float d = q.x * (k4.x + e4.x) + q.y * (k4.y + e4.y) +
                      q.z * (k4.z + e4.z) + q.w * (k4.w + e4.w);
            #pragma unroll
            for (int o = 16; o; o >>= 1) d += __shfl_xor_sync(0xffffffffu, d, o);
            float alpha = d * 0.08838834764831845f;

            float mn = fmaxf(m, alpha);
            float corr = __expf(m - mn);
            float p = __expf(alpha - mn);
            s = s * corr + p;
            acc.x = acc.x * corr + p * (v4.x + e4.x);
            acc.y = acc.y * corr + p * (v4.y + e4.y);
            acc.z = acc.z * corr + p * (v4.z + e4.z);
            acc.w = acc.w * corr + p * (v4.w + e4.w);
            m = mn;
        }
    }

    float inv = 1.f / (s + 1e-16f);
    float4 sk = *(const float4*)&out[(size_t)n * 128 + lane * 4];
    float4 r;
    r.x = acc.x * inv + sk.x;
    r.y = acc.y * inv + sk.y;
    r.z = acc.z * inv + sk.z;
    r.w = acc.w * inv + sk.w;
    r.x = r.x > 0.f ? r.x : expm1f(r.x);
    r.y = r.y > 0.f ? r.y : expm1f(r.y);
    r.z = r.z > 0.f ? r.z : expm1f(r.z);
    r.w = r.w > 0.f ? r.w : expm1f(r.w);
    *(float4*)&out[(size_t)n * 128 + lane * 4] = r;
}

// ---------------- launch -----------------------------------------------------
extern "C" void kernel_launch(void* const* d_in, const int* in_sizes, int n_in,
                              void* d_out, int out_size) {
    const float* x  = (const float*)d_in[0];
    const void*  ei = d_in[1];
    const float* ea = (const float*)d_in[2];
    const float* Wq = (const float*)d_in[3];
    const float* bq = (const float*)d_in[4];
    const float* Wk = (const float*)d_in[5];
    const float* bk = (const float*)d_in[6];
    const float* Wv = (const float*)d_in[7];
    const float* bv = (const float*)d_in[8];
    const float* We = (const float*)d_in[9];
    const float* be = (const float*)d_in[10];
    const float* Ws = (const float*)d_in[11];
    const float* bs = (const float*)d_in[12];
    float* out = (float*)d_out;

    float *dq;
    __half *dkh, *dvh;
    __nv_bfloat16 *wnh, *wnl;
    cudaGetSymbolAddress((void**)&dq, g_q);
    cudaGetSymbolAddress((void**)&dkh, g_kh);
    cudaGetSymbolAddress((void**)&dvh, g_vh);
    cudaGetSymbolAddress((void**)&wnh, g_Wn_hi);
    cudaGetSymbolAddress((void**)&wnl, g_Wn_lo);

    cudaFuncSetAttribute(gemm_mma_node, cudaFuncAttributeMaxDynamicSharedMemorySize, GEMM_SMEM);
    cudaFuncSetAttribute(edge_gemm_csr, cudaFuncAttributeMaxDynamicSharedMemorySize, GEMM_SMEM);

    detect_kernel<<<1, 256>>>((const unsigned int*)ei);
    zero_kernel<<<(NN + 255) / 256, 256>>>();
    prep_edges<<<(NE + 255) / 256, 256>>>(ei);
    convert_w<<<512, 256>>>(Wq, Wk, Wv, Ws, We);
    scan_kernel<<<1, 1024>>>();
    scatter_kernel<<<(NE + 255) / 256, 256>>>();

    dim3 ngrid((NN + 127) / 128, 4);
    gemm_mma_node<<<ngrid, 256, GEMM_SMEM>>>(x, NN, wnh, wnl,
                                             dq, dkh, dvh, out,
                                             bq, bk, bv, bs);
    edge_gemm_csr<<<NE / 128, 256, GEMM_SMEM>>>(ea, be);

    aggregate_kernel<<<(NN * 32 + 255) / 256, 256>>>(out);
}